// round 1
// baseline (speedup 1.0000x reference)
#include <cuda_runtime.h>
#include <cuda_bf16.h>

// Problem constants
#define BS1 32
#define BS2 128
#define NUM_EC 64
#define MEM_DIM 256
#define MLP_DIM 256
#define Q_DIM 256           // 4 * CONV_DIM
#define IN_DIM 512          // Q_DIM + MEM_DIM

// Scratch (device globals — no allocation allowed)
__device__ float g_att[BS1 * NUM_EC];                 // softmax_e(criteria·Wa_c)
__device__ float g_C1 [BS1 * NUM_EC * MLP_DIM];       // att * (criteria@Wm_c) + b_mlp
__device__ float g_PE [BS2 * MLP_DIM];                // ehr @ Wm_e

// ---------------------------------------------------------------------------
// K1: att[b,e] = softmax_e( dot(criteria[b,e,:], W_align[0:256]) )
// The logit_e[p] + b_align terms are constant over e -> cancel in softmax.
// grid = 32 (one block per b), block = 256 (4 threads per e)
// ---------------------------------------------------------------------------
__global__ void k_att(const float* __restrict__ crit,
                      const float* __restrict__ W_align) {
    const int b   = blockIdx.x;
    const int tid = threadIdx.x;
    const int e   = tid >> 2;
    const int q   = tid & 3;

    const float4* row = (const float4*)(crit + ((size_t)(b * NUM_EC + e)) * Q_DIM);
    const float4* wa  = (const float4*)W_align;

    float s = 0.f;
    #pragma unroll
    for (int i = 0; i < 16; ++i) {
        float4 c = row[q * 16 + i];
        float4 w = wa [q * 16 + i];
        s += c.x * w.x + c.y * w.y + c.z * w.z + c.w * w.w;
    }
    // reduce the quad (lanes e*4+q are contiguous within the warp)
    s += __shfl_xor_sync(0xffffffffu, s, 1);
    s += __shfl_xor_sync(0xffffffffu, s, 2);

    __shared__ float sm[NUM_EC];
    if (q == 0) sm[e] = s;
    __syncthreads();

    if (tid < 32) {
        float a  = sm[tid];
        float bb = sm[tid + 32];
        float m = fmaxf(a, bb);
        #pragma unroll
        for (int off = 16; off; off >>= 1)
            m = fmaxf(m, __shfl_xor_sync(0xffffffffu, m, off));
        float ea = expf(a - m);
        float eb = expf(bb - m);
        float ss = ea + eb;
        #pragma unroll
        for (int off = 16; off; off >>= 1)
            ss += __shfl_xor_sync(0xffffffffu, ss, off);
        float inv = 1.f / ss;
        g_att[b * NUM_EC + tid]      = ea * inv;
        g_att[b * NUM_EC + tid + 32] = eb * inv;
    }
}

// ---------------------------------------------------------------------------
// K2: C1[b,e,d] = att[b,e] * dot(criteria[b,e,:], Wm_c[:,d]) + b_mlp[d]
// grid = (32, 4)  (b, tile of 16 e's), block = 256 (one thread per d)
// ---------------------------------------------------------------------------
#define E_TILE 16
__global__ void k_c1(const float* __restrict__ crit,
                     const float* __restrict__ W_mlp,
                     const float* __restrict__ b_mlp) {
    const int b  = blockIdx.x;
    const int e0 = blockIdx.y * E_TILE;
    const int d  = threadIdx.x;

    __shared__ float4 cs[E_TILE][Q_DIM / 4];   // 16 KB

    // load criteria[b, e0..e0+15, :] (1024 float4, coalesced)
    const float4* src = (const float4*)crit + (size_t)(b * NUM_EC + e0) * (Q_DIM / 4);
    float4* dst = &cs[0][0];
    #pragma unroll
    for (int i = 0; i < E_TILE * (Q_DIM / 4) / 256; ++i)
        dst[d + i * 256] = src[d + i * 256];
    __syncthreads();

    float acc[E_TILE];
    #pragma unroll
    for (int e = 0; e < E_TILE; ++e) acc[e] = 0.f;

    const float* wcol = W_mlp + d;             // Wm_c column d (rows 0..255)
    #pragma unroll 2
    for (int k4 = 0; k4 < Q_DIM / 4; ++k4) {
        float w0 = wcol[(k4 * 4 + 0) * MLP_DIM];
        float w1 = wcol[(k4 * 4 + 1) * MLP_DIM];
        float w2 = wcol[(k4 * 4 + 2) * MLP_DIM];
        float w3 = wcol[(k4 * 4 + 3) * MLP_DIM];
        #pragma unroll
        for (int e = 0; e < E_TILE; ++e) {
            float4 c = cs[e][k4];              // broadcast LDS
            acc[e] += c.x * w0 + c.y * w1 + c.z * w2 + c.w * w3;
        }
    }

    const float bm = b_mlp[d];
    #pragma unroll
    for (int e = 0; e < E_TILE; ++e) {
        float a = g_att[b * NUM_EC + e0 + e];
        g_C1[((size_t)(b * NUM_EC + e0 + e)) * MLP_DIM + d] = a * acc[e] + bm;
    }
}

// ---------------------------------------------------------------------------
// K3: PE[p,d] = dot(ehr[p,:], Wm_e[:,d])   (Wm_e = W_mlp rows 256..511)
// grid = 128, block = 256
// ---------------------------------------------------------------------------
__global__ void k_pe(const float* __restrict__ ehr,
                     const float* __restrict__ W_mlp) {
    const int p = blockIdx.x;
    const int d = threadIdx.x;

    __shared__ float es[MEM_DIM];
    es[d] = ehr[(size_t)p * MEM_DIM + d];
    __syncthreads();

    const float* w = W_mlp + (size_t)Q_DIM * MLP_DIM + d;
    float acc = 0.f;
    #pragma unroll 4
    for (int k = 0; k < MEM_DIM; ++k)
        acc += es[k] * w[(size_t)k * MLP_DIM];
    g_PE[(size_t)p * MLP_DIM + d] = acc;
}

// ---------------------------------------------------------------------------
// K4 (main, store-bound): out[b,p,e,d] = C1[b,e,d] + att[b,e] * PE[p,d]
// grid = 32 * 32 (b, group of 4 p's), block = 256.
// p-tiling x4 amortizes the C1 read; __stcs streaming stores keep C1/PE in L2.
// ---------------------------------------------------------------------------
#define P_TILE 4
__global__ void k_main(float* __restrict__ out) {
    const int b   = blockIdx.x >> 5;
    const int pg  = blockIdx.x & 31;
    const int p0  = pg * P_TILE;
    const int tid = threadIdx.x;

    __shared__ float4 pes[P_TILE][MLP_DIM / 4];  // 4 KB
    __shared__ float  atts[NUM_EC];

    if (tid < NUM_EC) atts[tid] = g_att[b * NUM_EC + tid];
    {   // 256 threads load 4*64 = 256 float4 of PE
        int pp = tid >> 6, v = tid & 63;
        pes[pp][v] = ((const float4*)g_PE)[(size_t)(p0 + pp) * (MLP_DIM / 4) + v];
    }
    __syncthreads();

    const float4* c1 = (const float4*)g_C1 + (size_t)b * NUM_EC * (MLP_DIM / 4);
    float4* o = (float4*)out;
    const size_t base_b = (size_t)b * (BS2 * NUM_EC * (MLP_DIM / 4));

    #pragma unroll 4
    for (int i = tid; i < NUM_EC * (MLP_DIM / 4); i += 256) {
        const int e = i >> 6;
        const int v = i & 63;
        const float  a = atts[e];
        const float4 c = __ldg(&c1[i]);
        #pragma unroll
        for (int pp = 0; pp < P_TILE; ++pp) {
            float4 pe = pes[pp][v];
            float4 r;
            r.x = fmaf(a, pe.x, c.x);
            r.y = fmaf(a, pe.y, c.y);
            r.z = fmaf(a, pe.z, c.z);
            r.w = fmaf(a, pe.w, c.w);
            __stcs(&o[base_b + (size_t)(p0 + pp) * (NUM_EC * (MLP_DIM / 4)) + i], r);
        }
    }
}

// ---------------------------------------------------------------------------
// Launch. Inputs per metadata order:
// 0: ehr_vector (128*256)  1: criteria (32*64*256)  2: ec_mask (unused)
// 3: W_align (512)         4: b_align (unused, cancels in softmax)
// 5: W_mlp (512*256)       6: b_mlp (256)
// ---------------------------------------------------------------------------
extern "C" void kernel_launch(void* const* d_in, const int* in_sizes, int n_in,
                              void* d_out, int out_size) {
    const float* ehr     = (const float*)d_in[0];
    const float* crit    = (const float*)d_in[1];
    const float* W_align = (const float*)d_in[3];
    const float* W_mlp   = (const float*)d_in[5];
    const float* b_mlp   = (const float*)d_in[6];
    float* out = (float*)d_out;

    k_att <<<BS1, 256>>>(crit, W_align);
    k_c1  <<<dim3(BS1, NUM_EC / E_TILE), 256>>>(crit, W_mlp, b_mlp);
    k_pe  <<<BS2, 256>>>(ehr, W_mlp);
    k_main<<<BS1 * (BS2 / P_TILE), 256>>>(out);
}

// round 2
// speedup vs baseline: 1.2352x; 1.2352x over previous
#include <cuda_runtime.h>
#include <cuda_bf16.h>

// Problem constants
#define BS1 32
#define BS2 128
#define NUM_EC 64
#define MEM_DIM 256
#define MLP_DIM 256
#define Q_DIM 256           // 4 * CONV_DIM

// Scratch (device globals — allocation is forbidden)
__device__ float g_att[BS1 * NUM_EC];                 // softmax_e(criteria·Wa_c)
__device__ float g_PC [BS1 * NUM_EC * MLP_DIM];       // raw criteria @ Wm_c
__device__ float g_PE [BS2 * MLP_DIM];                // ehr @ Wm_e

// ---------------------------------------------------------------------------
// Fused prep kernel. All three pieces are independent (att is applied in
// k_main, so PC needs no att):
//   blocks [0,256):    PC[b,e,d] = dot(criteria[b,e,:], Wm_c[:,d])   (E_TILE=8)
//   blocks [256,288):  att[b,:]  = softmax_e(criteria[b,e,:]·Wa_c)
//   blocks [288,320):  PE[p,d]   = dot(ehr[p,:], Wm_e[:,d])          (4 p/blk)
// c1 blocks first so wave-1 is saturated with the FMA-heavy work.
// ---------------------------------------------------------------------------
#define C1_BLOCKS   256
#define ATT_BLOCKS  32
#define PE_BLOCKS   32
#define E_TILE      8
#define PE_P_TILE   4

__global__ void __launch_bounds__(256) k_prep(const float* __restrict__ ehr,
                                              const float* __restrict__ crit,
                                              const float* __restrict__ W_align,
                                              const float* __restrict__ W_mlp) {
    __shared__ __align__(16) float sbuf[E_TILE * Q_DIM];   // 8 KB, reused by all parts
    const int bid = blockIdx.x;
    const int tid = threadIdx.x;

    if (bid < C1_BLOCKS) {
        // ----- PC: criteria @ Wm_c (raw) -----
        const int b  = bid >> 3;
        const int e0 = (bid & 7) * E_TILE;
        const int d  = tid;

        float4* cs = (float4*)sbuf;            // [E_TILE][Q_DIM/4]
        const float4* src = (const float4*)crit + (size_t)(b * NUM_EC + e0) * (Q_DIM / 4);
        #pragma unroll
        for (int i = 0; i < E_TILE * (Q_DIM / 4) / 256; ++i)
            cs[d + i * 256] = src[d + i * 256];
        __syncthreads();

        float acc[E_TILE];
        #pragma unroll
        for (int e = 0; e < E_TILE; ++e) acc[e] = 0.f;

        const float* wcol = W_mlp + d;
        #pragma unroll 4
        for (int k4 = 0; k4 < Q_DIM / 4; ++k4) {
            float w0 = wcol[(k4 * 4 + 0) * MLP_DIM];
            float w1 = wcol[(k4 * 4 + 1) * MLP_DIM];
            float w2 = wcol[(k4 * 4 + 2) * MLP_DIM];
            float w3 = wcol[(k4 * 4 + 3) * MLP_DIM];
            #pragma unroll
            for (int e = 0; e < E_TILE; ++e) {
                float4 c = cs[e * (Q_DIM / 4) + k4];
                acc[e] += c.x * w0 + c.y * w1 + c.z * w2 + c.w * w3;
            }
        }
        #pragma unroll
        for (int e = 0; e < E_TILE; ++e)
            g_PC[((size_t)(b * NUM_EC + e0 + e)) * MLP_DIM + d] = acc[e];

    } else if (bid < C1_BLOCKS + ATT_BLOCKS) {
        // ----- att: softmax over e of criteria·Wa_c -----
        // logit_e[p] + b_align are constant over e -> cancel in softmax.
        const int b = bid - C1_BLOCKS;
        const int e = tid >> 2;
        const int q = tid & 3;

        const float4* row = (const float4*)(crit + ((size_t)(b * NUM_EC + e)) * Q_DIM);
        const float4* wa  = (const float4*)W_align;

        float s = 0.f;
        #pragma unroll
        for (int i = 0; i < 16; ++i) {
            float4 c = row[q * 16 + i];
            float4 w = wa [q * 16 + i];
            s += c.x * w.x + c.y * w.y + c.z * w.z + c.w * w.w;
        }
        s += __shfl_xor_sync(0xffffffffu, s, 1);
        s += __shfl_xor_sync(0xffffffffu, s, 2);

        float* sm = sbuf;
        if (q == 0) sm[e] = s;
        __syncthreads();

        if (tid < 32) {
            float a  = sm[tid];
            float bb = sm[tid + 32];
            float m = fmaxf(a, bb);
            #pragma unroll
            for (int off = 16; off; off >>= 1)
                m = fmaxf(m, __shfl_xor_sync(0xffffffffu, m, off));
            float ea = expf(a - m);
            float eb = expf(bb - m);
            float ss = ea + eb;
            #pragma unroll
            for (int off = 16; off; off >>= 1)
                ss += __shfl_xor_sync(0xffffffffu, ss, off);
            float inv = 1.f / ss;
            g_att[b * NUM_EC + tid]      = ea * inv;
            g_att[b * NUM_EC + tid + 32] = eb * inv;
        }

    } else {
        // ----- PE: ehr @ Wm_e -----
        const int pg = bid - (C1_BLOCKS + ATT_BLOCKS);
        const int p0 = pg * PE_P_TILE;
        const int d  = tid;

        float* es = sbuf;                      // [PE_P_TILE][MEM_DIM]
        #pragma unroll
        for (int i = 0; i < PE_P_TILE; ++i)
            es[i * MEM_DIM + d] = ehr[(size_t)(p0 + i) * MEM_DIM + d];
        __syncthreads();

        float acc[PE_P_TILE];
        #pragma unroll
        for (int i = 0; i < PE_P_TILE; ++i) acc[i] = 0.f;

        const float* w = W_mlp + (size_t)Q_DIM * MLP_DIM + d;
        #pragma unroll 4
        for (int k = 0; k < MEM_DIM; ++k) {
            float wv = w[(size_t)k * MLP_DIM];
            #pragma unroll
            for (int i = 0; i < PE_P_TILE; ++i)
                acc[i] += es[i * MEM_DIM + k] * wv;
        }
        #pragma unroll
        for (int i = 0; i < PE_P_TILE; ++i)
            g_PE[(size_t)(p0 + i) * MLP_DIM + d] = acc[i];
    }
}

// ---------------------------------------------------------------------------
// Main (store-bound): out[b,p,e,d] = att[b,e] * (PC[b,e,d] + PE[p,d]) + b_mlp[d]
// grid = 32 b * 16 p-groups (P_TILE=8), block = 256.
// __stcs streaming stores: output is never re-read; keep PC/PE resident in L2.
// ---------------------------------------------------------------------------
#define P_TILE 8
__global__ void __launch_bounds__(256) k_main(float* __restrict__ out,
                                              const float* __restrict__ b_mlp) {
    const int b   = blockIdx.x >> 4;
    const int pg  = blockIdx.x & 15;
    const int p0  = pg * P_TILE;
    const int tid = threadIdx.x;

    __shared__ float4 pes[P_TILE][MLP_DIM / 4];   // 8 KB
    __shared__ float  atts[NUM_EC];
    __shared__ float4 bm4[MLP_DIM / 4];           // 1 KB

    {   // 256 threads load 8*64 = 512 float4 of PE
        const float4* pe_src = (const float4*)g_PE + (size_t)p0 * (MLP_DIM / 4);
        ((float4*)pes)[tid]       = pe_src[tid];
        ((float4*)pes)[tid + 256] = pe_src[tid + 256];
    }
    if (tid < NUM_EC)      atts[tid] = g_att[b * NUM_EC + tid];
    else if (tid < 2 * NUM_EC) bm4[tid - NUM_EC] = ((const float4*)b_mlp)[tid - NUM_EC];
    __syncthreads();

    const float4* pc = (const float4*)g_PC + (size_t)b * NUM_EC * (MLP_DIM / 4);
    float4* o = (float4*)out;
    const size_t base_b = (size_t)b * (BS2 * NUM_EC * (MLP_DIM / 4));

    #pragma unroll 4
    for (int i = tid; i < NUM_EC * (MLP_DIM / 4); i += 256) {
        const int e = i >> 6;
        const int v = i & 63;
        const float  a  = atts[e];
        const float4 c  = __ldg(&pc[i]);
        const float4 bm = bm4[v];
        #pragma unroll
        for (int pp = 0; pp < P_TILE; ++pp) {
            float4 pe = pes[pp][v];
            float4 r;
            r.x = fmaf(a, c.x + pe.x, bm.x);
            r.y = fmaf(a, c.y + pe.y, bm.y);
            r.z = fmaf(a, c.z + pe.z, bm.z);
            r.w = fmaf(a, c.w + pe.w, bm.w);
            __stcs(&o[base_b + (size_t)(p0 + pp) * (NUM_EC * (MLP_DIM / 4)) + i], r);
        }
    }
}

// ---------------------------------------------------------------------------
// Inputs per metadata order:
// 0: ehr_vector (128*256)  1: criteria (32*64*256)  2: ec_mask (unused)
// 3: W_align (512)         4: b_align (unused, cancels in softmax)
// 5: W_mlp (512*256)       6: b_mlp (256)
// ---------------------------------------------------------------------------
extern "C" void kernel_launch(void* const* d_in, const int* in_sizes, int n_in,
                              void* d_out, int out_size) {
    const float* ehr     = (const float*)d_in[0];
    const float* crit    = (const float*)d_in[1];
    const float* W_align = (const float*)d_in[3];
    const float* W_mlp   = (const float*)d_in[5];
    const float* b_mlp   = (const float*)d_in[6];
    float* out = (float*)d_out;

    k_prep<<<C1_BLOCKS + ATT_BLOCKS + PE_BLOCKS, 256>>>(ehr, crit, W_align, W_mlp);
    k_main<<<BS1 * (BS2 / P_TILE), 256>>>(out, b_mlp);
}

// round 3
// speedup vs baseline: 1.3269x; 1.0743x over previous
#include <cuda_runtime.h>
#include <cuda_bf16.h>

// Problem constants
#define BS1 32
#define BS2 128
#define NUM_EC 64
#define MEM_DIM 256
#define MLP_DIM 256
#define Q_DIM 256           // 4 * CONV_DIM

// Scratch (device globals — allocation is forbidden)
__device__ float g_att[BS1 * NUM_EC];                 // softmax_e(criteria·Wa_c)
__device__ float g_PC [BS1 * NUM_EC * MLP_DIM];       // raw criteria @ Wm_c
__device__ float g_PE [BS2 * MLP_DIM];                // ehr @ Wm_e

// ---------------------------------------------------------------------------
// Fused prep kernel (single wave):
//   blocks [0,512):    PC[b,e,d] = dot(criteria[b,e,:], Wm_c[:,d])
//                      grid split: 32 b x 8 e-tiles(8) x 2 d-halves(128),
//                      each block k-split x2 across threads, smem reduce.
//   blocks [512,544):  att[b,:]  = softmax_e(criteria[b,e,:]·Wa_c)
//   blocks [544,576):  PE[p,d]   = dot(ehr[p,:], Wm_e[:,d])   (4 p / block)
// ---------------------------------------------------------------------------
#define C1_BLOCKS   512
#define ATT_BLOCKS  32
#define PE_BLOCKS   32
#define E_TILE      8
#define PE_P_TILE   4

__global__ void __launch_bounds__(256) k_prep(const float* __restrict__ ehr,
                                              const float* __restrict__ crit,
                                              const float* __restrict__ W_align,
                                              const float* __restrict__ W_mlp) {
    __shared__ __align__(16) float sbuf[2048];   // 8 KB, reused by all roles
    const int bid = blockIdx.x;
    const int tid = threadIdx.x;

    if (bid < C1_BLOCKS) {
        // ----- PC: criteria @ Wm_c (raw, att applied in k_main) -----
        const int b  = bid >> 4;
        const int et = (bid >> 1) & 7;
        const int dh = bid & 1;
        const int e0 = et * E_TILE;
        const int dl = tid & 127;          // local d within half
        const int kh = tid >> 7;           // k-half (0/1)
        const int d  = dh * 128 + dl;

        // load criteria[b, e0..e0+7, :]  (512 float4, 2 per thread)
        float4* cs = (float4*)sbuf;        // [E_TILE][Q_DIM/4]
        const float4* src = (const float4*)crit + (size_t)(b * NUM_EC + e0) * (Q_DIM / 4);
        cs[tid]       = src[tid];
        cs[tid + 256] = src[tid + 256];
        __syncthreads();

        float acc[E_TILE];
        #pragma unroll
        for (int e = 0; e < E_TILE; ++e) acc[e] = 0.f;

        const float* wcol = W_mlp + d;
        const int k4base = kh * 32;        // 32 float4-groups = 128 k per half
        #pragma unroll 4
        for (int k4 = k4base; k4 < k4base + 32; ++k4) {
            float w0 = wcol[(k4 * 4 + 0) * MLP_DIM];
            float w1 = wcol[(k4 * 4 + 1) * MLP_DIM];
            float w2 = wcol[(k4 * 4 + 2) * MLP_DIM];
            float w3 = wcol[(k4 * 4 + 3) * MLP_DIM];
            #pragma unroll
            for (int e = 0; e < E_TILE; ++e) {
                float4 c = cs[e * (Q_DIM / 4) + k4];
                acc[e] += c.x * w0 + c.y * w1 + c.z * w2 + c.w * w3;
            }
        }
        __syncthreads();
        // partial[kh][e][dl] -> reduce across kh
        float* part = sbuf;                // [2][E_TILE][128]
        #pragma unroll
        for (int e = 0; e < E_TILE; ++e)
            part[(kh * E_TILE + e) * 128 + dl] = acc[e];
        __syncthreads();

        // 1024 outputs, 256 threads -> 4 each
        #pragma unroll
        for (int i = 0; i < 4; ++i) {
            const int idx = tid + i * 256;        // e*128 + dl
            const int e  = idx >> 7;
            const int dd = idx & 127;
            float v = part[e * 128 + dd] + part[(E_TILE + e) * 128 + dd];
            g_PC[((size_t)(b * NUM_EC + e0 + e)) * MLP_DIM + dh * 128 + dd] = v;
        }

    } else if (bid < C1_BLOCKS + ATT_BLOCKS) {
        // ----- att: softmax over e of criteria·Wa_c -----
        // logit_e[p] + b_align are constant over e -> cancel in softmax.
        const int b = bid - C1_BLOCKS;
        const int e = tid >> 2;
        const int q = tid & 3;

        const float4* row = (const float4*)(crit + ((size_t)(b * NUM_EC + e)) * Q_DIM);
        const float4* wa  = (const float4*)W_align;

        float s = 0.f;
        #pragma unroll
        for (int i = 0; i < 16; ++i) {
            float4 c = row[q * 16 + i];
            float4 w = wa [q * 16 + i];
            s += c.x * w.x + c.y * w.y + c.z * w.z + c.w * w.w;
        }
        s += __shfl_xor_sync(0xffffffffu, s, 1);
        s += __shfl_xor_sync(0xffffffffu, s, 2);

        float* sm = sbuf;
        if (q == 0) sm[e] = s;
        __syncthreads();

        if (tid < 32) {
            float a  = sm[tid];
            float bb = sm[tid + 32];
            float m = fmaxf(a, bb);
            #pragma unroll
            for (int off = 16; off; off >>= 1)
                m = fmaxf(m, __shfl_xor_sync(0xffffffffu, m, off));
            float ea = expf(a - m);
            float eb = expf(bb - m);
            float ss = ea + eb;
            #pragma unroll
            for (int off = 16; off; off >>= 1)
                ss += __shfl_xor_sync(0xffffffffu, ss, off);
            float inv = 1.f / ss;
            g_att[b * NUM_EC + tid]      = ea * inv;
            g_att[b * NUM_EC + tid + 32] = eb * inv;
        }

    } else {
        // ----- PE: ehr @ Wm_e -----
        const int pg = bid - (C1_BLOCKS + ATT_BLOCKS);
        const int p0 = pg * PE_P_TILE;
        const int d  = tid;

        float* es = sbuf;                  // [PE_P_TILE][MEM_DIM]
        #pragma unroll
        for (int i = 0; i < PE_P_TILE; ++i)
            es[i * MEM_DIM + d] = ehr[(size_t)(p0 + i) * MEM_DIM + d];
        __syncthreads();

        float acc[PE_P_TILE];
        #pragma unroll
        for (int i = 0; i < PE_P_TILE; ++i) acc[i] = 0.f;

        const float* w = W_mlp + (size_t)Q_DIM * MLP_DIM + d;
        #pragma unroll 4
        for (int k = 0; k < MEM_DIM; ++k) {
            float wv = w[(size_t)k * MLP_DIM];
            #pragma unroll
            for (int i = 0; i < PE_P_TILE; ++i)
                acc[i] += es[i * MEM_DIM + k] * wv;
        }
        #pragma unroll
        for (int i = 0; i < PE_P_TILE; ++i)
            g_PE[(size_t)(p0 + i) * MLP_DIM + d] = acc[i];
    }
}

// ---------------------------------------------------------------------------
// Main (store-bound): out[b,p,e,d] = att[b,e] * (PC[b,e,d] + PE[p,d]) + b_mlp[d]
// grid = 32 b x 32 p-groups (P_TILE=4), block = 256, target 6 blocks/SM.
// __stcs streaming stores: output is never re-read.
// ---------------------------------------------------------------------------
#define P_TILE 4
__global__ void __launch_bounds__(256, 6) k_main(float* __restrict__ out,
                                                 const float* __restrict__ b_mlp) {
    const int b   = blockIdx.x >> 5;
    const int pg  = blockIdx.x & 31;
    const int p0  = pg * P_TILE;
    const int tid = threadIdx.x;

    __shared__ float4 pes[P_TILE][MLP_DIM / 4];   // 4 KB
    __shared__ float  atts[NUM_EC];
    __shared__ float4 bm4[MLP_DIM / 4];           // 1 KB

    {   // 256 threads load 4*64 = 256 float4 of PE
        const float4* pe_src = (const float4*)g_PE + (size_t)p0 * (MLP_DIM / 4);
        ((float4*)pes)[tid] = pe_src[tid];
    }
    if (tid < NUM_EC)          atts[tid] = g_att[b * NUM_EC + tid];
    else if (tid < 2 * NUM_EC) bm4[tid - NUM_EC] = ((const float4*)b_mlp)[tid - NUM_EC];
    __syncthreads();

    const float4* pc = (const float4*)g_PC + (size_t)b * NUM_EC * (MLP_DIM / 4);
    float4* o = (float4*)out;
    const size_t base_b = (size_t)b * (BS2 * NUM_EC * (MLP_DIM / 4));

    #pragma unroll 4
    for (int i = tid; i < NUM_EC * (MLP_DIM / 4); i += 256) {
        const int e = i >> 6;
        const int v = i & 63;
        const float  a  = atts[e];
        const float4 c  = __ldg(&pc[i]);
        const float4 bm = bm4[v];
        #pragma unroll
        for (int pp = 0; pp < P_TILE; ++pp) {
            float4 pe = pes[pp][v];
            float4 r;
            r.x = fmaf(a, c.x + pe.x, bm.x);
            r.y = fmaf(a, c.y + pe.y, bm.y);
            r.z = fmaf(a, c.z + pe.z, bm.z);
            r.w = fmaf(a, c.w + pe.w, bm.w);
            __stcs(&o[base_b + (size_t)(p0 + pp) * (NUM_EC * (MLP_DIM / 4)) + i], r);
        }
    }
}

// ---------------------------------------------------------------------------
// Inputs per metadata order:
// 0: ehr_vector (128*256)  1: criteria (32*64*256)  2: ec_mask (unused)
// 3: W_align (512)         4: b_align (unused, cancels in softmax)
// 5: W_mlp (512*256)       6: b_mlp (256)
// ---------------------------------------------------------------------------
extern "C" void kernel_launch(void* const* d_in, const int* in_sizes, int n_in,
                              void* d_out, int out_size) {
    const float* ehr     = (const float*)d_in[0];
    const float* crit    = (const float*)d_in[1];
    const float* W_align = (const float*)d_in[3];
    const float* W_mlp   = (const float*)d_in[5];
    const float* b_mlp   = (const float*)d_in[6];
    float* out = (float*)d_out;

    k_prep<<<C1_BLOCKS + ATT_BLOCKS + PE_BLOCKS, 256>>>(ehr, crit, W_align, W_mlp);
    k_main<<<BS1 * (BS2 / P_TILE), 256>>>(out, b_mlp);
}